// round 1
// baseline (speedup 1.0000x reference)
#include <cuda_runtime.h>
#include <cuda_bf16.h>
#include <math.h>

#define BB 4
#define TT 1024
#define DD 1024
#define HH 16
#define HD 64
#define LL 8
#define VV 50257
#define FF 4096
#define D3 3072
#define BT 4096   // B*T

// ---------------- scratch (static device globals; no allocation) ----------------
__device__ float g_x  [(size_t)BT * DD];   // residual stream
__device__ float g_xn [(size_t)BT * DD];   // layernorm output
__device__ float g_tmp[(size_t)BT * FF];   // qkv ([BT,3072]) or mlp hidden ([BT,4096])
__device__ float g_y  [(size_t)BT * DD];   // attention output (pre-proj)
__device__ float g_S  [(size_t)BB * HH * TT * TT]; // attention scores/probs
__device__ float g_nll[BT];

// ---------------- reductions ----------------
__device__ __forceinline__ float blockReduceSum(float v, float* red) {
    int tid = threadIdx.x;
    red[tid] = v; __syncthreads();
    for (int s = blockDim.x >> 1; s > 0; s >>= 1) {
        if (tid < s) red[tid] += red[tid + s];
        __syncthreads();
    }
    float r = red[0]; __syncthreads();
    return r;
}
__device__ __forceinline__ float blockReduceMax(float v, float* red) {
    int tid = threadIdx.x;
    red[tid] = v; __syncthreads();
    for (int s = blockDim.x >> 1; s > 0; s >>= 1) {
        if (tid < s) red[tid] = fmaxf(red[tid], red[tid + s]);
        __syncthreads();
    }
    float r = red[0]; __syncthreads();
    return r;
}

// ---------------- embedding ----------------
__global__ void embed_kernel(const int* __restrict__ ctx,
                             const float* __restrict__ wte,
                             const float* __restrict__ wpe,
                             float* __restrict__ x) {
    int r = blockIdx.x;                  // 0..BT-1
    int tok = ctx[r];
    int t = r & (TT - 1);
    const float* we = wte + (size_t)tok * DD;
    const float* wp = wpe + (size_t)t * DD;
    float* xr = x + (size_t)r * DD;
    for (int c = threadIdx.x; c < DD; c += blockDim.x)
        xr[c] = we[c] + wp[c];
}

// ---------------- layernorm (one block per row of 1024) ----------------
__global__ void layernorm_kernel(const float* __restrict__ x,
                                 const float* __restrict__ g,
                                 const float* __restrict__ b,
                                 float* __restrict__ o) {
    __shared__ float red[256];
    int r = blockIdx.x;
    const float* xr = x + (size_t)r * DD;
    float v[4];
    float s = 0.f, ss = 0.f;
#pragma unroll
    for (int k = 0; k < 4; k++) {
        int c = threadIdx.x + k * 256;
        v[k] = xr[c];
        s += v[k];
        ss += v[k] * v[k];
    }
    s  = blockReduceSum(s,  red);
    ss = blockReduceSum(ss, red);
    float mean = s * (1.0f / DD);
    float var  = ss * (1.0f / DD) - mean * mean;
    float rstd = rsqrtf(var + 1e-5f);
    float* orow = o + (size_t)r * DD;
#pragma unroll
    for (int k = 0; k < 4; k++) {
        int c = threadIdx.x + k * 256;
        orow[c] = (v[k] - mean) * rstd * g[c] + b[c];
    }
}

// ---------------- SGEMM: C[M,N] = A[M,K] @ W[N,K]^T  (optionally += ) --------
// BM=128, BN=128, BK=8, 256 threads, 8x8 per thread. M % 128 == 0, K % 8 == 0.
template <bool ADD>
__global__ void sgemm_nt(const float* __restrict__ A,
                         const float* __restrict__ W,
                         float* __restrict__ C,
                         int M, int N, int K) {
    __shared__ float As[8][128];
    __shared__ float Ws[8][128];
    int tid = threadIdx.x;
    int m0 = blockIdx.y * 128;
    int n0 = blockIdx.x * 128;
    int lr = tid >> 1;            // 0..127
    int lk = (tid & 1) * 4;       // 0 or 4
    int ty = tid >> 4;            // 0..15
    int tx = tid & 15;            // 0..15

    const float* Aptr = A + (size_t)(m0 + lr) * K + lk;
    int wrow = n0 + lr;
    const float* Wptr = W + (size_t)wrow * K + lk;
    bool wok = (wrow < N);

    float acc[8][8];
#pragma unroll
    for (int i = 0; i < 8; i++)
#pragma unroll
        for (int j = 0; j < 8; j++) acc[i][j] = 0.f;

    for (int k0 = 0; k0 < K; k0 += 8) {
        float4 av = *(const float4*)(Aptr + k0);
        float4 wv = wok ? *(const float4*)(Wptr + k0) : make_float4(0.f, 0.f, 0.f, 0.f);
        __syncthreads();
        As[lk + 0][lr] = av.x; As[lk + 1][lr] = av.y;
        As[lk + 2][lr] = av.z; As[lk + 3][lr] = av.w;
        Ws[lk + 0][lr] = wv.x; Ws[lk + 1][lr] = wv.y;
        Ws[lk + 2][lr] = wv.z; Ws[lk + 3][lr] = wv.w;
        __syncthreads();
#pragma unroll
        for (int kk = 0; kk < 8; kk++) {
            float ra[8], rb[8];
#pragma unroll
            for (int i = 0; i < 8; i++) ra[i] = As[kk][ty * 8 + i];
#pragma unroll
            for (int j = 0; j < 8; j++) rb[j] = Ws[kk][tx * 8 + j];
#pragma unroll
            for (int i = 0; i < 8; i++)
#pragma unroll
                for (int j = 0; j < 8; j++) acc[i][j] = fmaf(ra[i], rb[j], acc[i][j]);
        }
    }

#pragma unroll
    for (int i = 0; i < 8; i++) {
        int m = m0 + ty * 8 + i;
        float* crow = C + (size_t)m * N;
#pragma unroll
        for (int j = 0; j < 8; j++) {
            int n = n0 + tx * 8 + j;
            if (n < N) {
                if (ADD) crow[n] += acc[i][j];
                else     crow[n]  = acc[i][j];
            }
        }
    }
}

// ---------------- attention scores: S = Q K^T / 8 (causal tiles only) -------
// grid (nt=T/64, mt=T/64, B*H), 256 threads, 64x64 tile, BK=16
__global__ void attn_scores(const float* __restrict__ qkv, float* __restrict__ S) {
    int mt = blockIdx.y, nt = blockIdx.x;
    if (nt > mt) return;
    int bh = blockIdx.z;
    int b = bh >> 4, h = bh & 15;
    __shared__ float Qs[16][64];
    __shared__ float Ks[16][64];
    int tid = threadIdx.x;
    int lr = tid >> 2;            // 0..63
    int lk = (tid & 3) * 4;       // 0,4,8,12
    int ty = tid >> 4, tx = tid & 15;

    const float* qb = qkv + ((size_t)(b * TT + mt * 64 + lr)) * D3 + h * HD + lk;
    const float* kb = qkv + ((size_t)(b * TT + nt * 64 + lr)) * D3 + DD + h * HD + lk;

    float acc[4][4];
#pragma unroll
    for (int i = 0; i < 4; i++)
#pragma unroll
        for (int j = 0; j < 4; j++) acc[i][j] = 0.f;

    for (int k0 = 0; k0 < HD; k0 += 16) {
        float4 qv = *(const float4*)(qb + k0);
        float4 kv = *(const float4*)(kb + k0);
        __syncthreads();
        Qs[lk + 0][lr] = qv.x; Qs[lk + 1][lr] = qv.y;
        Qs[lk + 2][lr] = qv.z; Qs[lk + 3][lr] = qv.w;
        Ks[lk + 0][lr] = kv.x; Ks[lk + 1][lr] = kv.y;
        Ks[lk + 2][lr] = kv.z; Ks[lk + 3][lr] = kv.w;
        __syncthreads();
#pragma unroll
        for (int kk = 0; kk < 16; kk++) {
            float ra[4], rb[4];
#pragma unroll
            for (int i = 0; i < 4; i++) ra[i] = Qs[kk][ty * 4 + i];
#pragma unroll
            for (int j = 0; j < 4; j++) rb[j] = Ks[kk][tx * 4 + j];
#pragma unroll
            for (int i = 0; i < 4; i++)
#pragma unroll
                for (int j = 0; j < 4; j++) acc[i][j] = fmaf(ra[i], rb[j], acc[i][j]);
        }
    }
#pragma unroll
    for (int i = 0; i < 4; i++) {
        int t = mt * 64 + ty * 4 + i;
        float* srow = S + ((size_t)bh * TT + t) * TT;
#pragma unroll
        for (int j = 0; j < 4; j++) {
            int s = nt * 64 + tx * 4 + j;
            srow[s] = acc[i][j] * 0.125f;
        }
    }
}

// ---------------- causal softmax over row, zero-fill to 64-tile boundary ----
__global__ void softmax_causal(float* __restrict__ S) {
    __shared__ float red[128];
    int row = blockIdx.x;                 // 0..B*H*T-1
    int t = row & (TT - 1);
    float* p = S + (size_t)row * TT;
    int len = t + 1;
    int tid = threadIdx.x;

    float mx = -INFINITY;
    for (int i = tid; i < len; i += 128) mx = fmaxf(mx, p[i]);
    mx = blockReduceMax(mx, red);

    float s = 0.f;
    for (int i = tid; i < len; i += 128) {
        float e = expf(p[i] - mx);
        p[i] = e;
        s += e;
    }
    s = blockReduceSum(s, red);
    float inv = 1.0f / s;
    for (int i = tid; i < len; i += 128) p[i] *= inv;
    int fill = ((t >> 6) + 1) << 6;       // zero up to tile boundary
    for (int i = len + tid; i < fill; i += 128) p[i] = 0.f;
}

// ---------------- attention PV: y = P @ V ----------------
// grid (1, mt=T/64, B*H), 256 threads, out tile 64(t) x 64(hd)
__global__ void attn_pv(const float* __restrict__ S,
                        const float* __restrict__ qkv,
                        float* __restrict__ y) {
    int mt = blockIdx.y;
    int bh = blockIdx.z;
    int b = bh >> 4, h = bh & 15;
    __shared__ float Ps[16][64];
    __shared__ float Vs[16][64];
    int tid = threadIdx.x;
    int ty = tid >> 4, tx = tid & 15;

    int lr = tid >> 2;            // 0..63  (P rows)
    int ls = (tid & 3) * 4;       // P s-offset
    int vk = tid >> 4;            // 0..15  (V rows within chunk)
    int vd = (tid & 15) * 4;      // V dim offset

    const float* Pb = S + ((size_t)bh * TT + mt * 64 + lr) * TT + ls;
    const float* Vb = qkv + ((size_t)(b * TT + vk)) * D3 + 2 * DD + h * HD + vd;

    float acc[4][4];
#pragma unroll
    for (int i = 0; i < 4; i++)
#pragma unroll
        for (int j = 0; j < 4; j++) acc[i][j] = 0.f;

    int send = (mt + 1) * 64;
    for (int s0 = 0; s0 < send; s0 += 16) {
        float4 pv = *(const float4*)(Pb + s0);
        float4 vv = *(const float4*)(Vb + (size_t)s0 * D3);
        __syncthreads();
        Ps[ls + 0][lr] = pv.x; Ps[ls + 1][lr] = pv.y;
        Ps[ls + 2][lr] = pv.z; Ps[ls + 3][lr] = pv.w;
        Vs[vk][vd + 0] = vv.x; Vs[vk][vd + 1] = vv.y;
        Vs[vk][vd + 2] = vv.z; Vs[vk][vd + 3] = vv.w;
        __syncthreads();
#pragma unroll
        for (int kk = 0; kk < 16; kk++) {
            float ra[4], rb[4];
#pragma unroll
            for (int i = 0; i < 4; i++) ra[i] = Ps[kk][ty * 4 + i];
#pragma unroll
            for (int j = 0; j < 4; j++) rb[j] = Vs[kk][tx * 4 + j];
#pragma unroll
            for (int i = 0; i < 4; i++)
#pragma unroll
                for (int j = 0; j < 4; j++) acc[i][j] = fmaf(ra[i], rb[j], acc[i][j]);
        }
    }
#pragma unroll
    for (int i = 0; i < 4; i++) {
        int t = mt * 64 + ty * 4 + i;
        float* yr = y + ((size_t)(b * TT + t)) * DD + h * HD;
#pragma unroll
        for (int j = 0; j < 4; j++) yr[tx * 4 + j] = acc[i][j];
    }
}

// ---------------- exact GELU ----------------
__global__ void gelu_kernel(float* __restrict__ x) {
    size_t i = ((size_t)blockIdx.x * 256 + threadIdx.x) * 4;
    float4 v = *(float4*)(x + i);
    v.x = 0.5f * v.x * (1.0f + erff(v.x * 0.70710678118654752f));
    v.y = 0.5f * v.y * (1.0f + erff(v.y * 0.70710678118654752f));
    v.z = 0.5f * v.z * (1.0f + erff(v.z * 0.70710678118654752f));
    v.w = 0.5f * v.w * (1.0f + erff(v.w * 0.70710678118654752f));
    *(float4*)(x + i) = v;
}

// ---------------- cross entropy ----------------
__global__ void loss_row_kernel(const float* __restrict__ logits,
                                const int* __restrict__ targets,
                                float* __restrict__ nll) {
    __shared__ float red[256];
    int r = blockIdx.x;
    const float* p = logits + (size_t)r * VV;
    int tid = threadIdx.x;
    float mx = -INFINITY;
    for (int i = tid; i < VV; i += 256) mx = fmaxf(mx, p[i]);
    mx = blockReduceMax(mx, red);
    float s = 0.f;
    for (int i = tid; i < VV; i += 256) s += expf(p[i] - mx);
    s = blockReduceSum(s, red);
    if (tid == 0) {
        int tg = targets[r];
        nll[r] = (tg < 0) ? 0.f : (logf(s) + mx - p[tg]);
    }
}

__global__ void loss_reduce_kernel(const float* __restrict__ nll,
                                   const int* __restrict__ targets,
                                   float* __restrict__ out,
                                   long long idx1, long long idx2, long long out_size) {
    __shared__ float red[256];
    __shared__ float redc[256];
    int tid = threadIdx.x;
    float acc = 0.f, cnt = 0.f;
    for (int i = tid; i < BT; i += 256) {
        acc += nll[i];
        cnt += (targets[i] != -1) ? 1.f : 0.f;
    }
    red[tid] = acc; redc[tid] = cnt; __syncthreads();
    for (int s = 128; s > 0; s >>= 1) {
        if (tid < s) { red[tid] += red[tid + s]; redc[tid] += redc[tid + s]; }
        __syncthreads();
    }
    if (tid == 0) {
        float loss = red[0] / fmaxf(redc[0], 1.f);
        if (idx1 >= 0 && idx1 < out_size) out[idx1] = loss;
        if (idx2 != idx1 && idx2 >= (long long)BT * VV && idx2 < out_size) out[idx2] = loss;
    }
}

// ---------------- driver ----------------
extern "C" void kernel_launch(void* const* d_in, const int* in_sizes, int n_in,
                              void* d_out, int out_size) {
    const int*   context = (const int*)  d_in[0];
    const int*   targets = (const int*)  d_in[1];
    const float* wte     = (const float*)d_in[2];
    const float* wpe     = (const float*)d_in[3];
    const float* ln1_g   = (const float*)d_in[4];
    const float* ln1_b   = (const float*)d_in[5];
    const float* w_attn  = (const float*)d_in[6];
    const float* w_proj  = (const float*)d_in[7];
    const float* ln2_g   = (const float*)d_in[8];
    const float* ln2_b   = (const float*)d_in[9];
    const float* w_fc    = (const float*)d_in[10];
    const float* w_out   = (const float*)d_in[11];
    const float* lnf_g   = (const float*)d_in[12];
    const float* lnf_b   = (const float*)d_in[13];
    float* out = (float*)d_out;

    float *px, *pxn, *ptmp, *py, *pS, *pnll;
    cudaGetSymbolAddress((void**)&px,   g_x);
    cudaGetSymbolAddress((void**)&pxn,  g_xn);
    cudaGetSymbolAddress((void**)&ptmp, g_tmp);
    cudaGetSymbolAddress((void**)&py,   g_y);
    cudaGetSymbolAddress((void**)&pS,   g_S);
    cudaGetSymbolAddress((void**)&pnll, g_nll);

    embed_kernel<<<BT, 256>>>(context, wte, wpe, px);

    for (int l = 0; l < LL; l++) {
        // attention block
        layernorm_kernel<<<BT, 256>>>(px, ln1_g + l * DD, ln1_b + l * DD, pxn);
        sgemm_nt<false><<<dim3(D3 / 128, BT / 128), 256>>>(
            pxn, w_attn + (size_t)l * D3 * DD, ptmp, BT, D3, DD);
        attn_scores<<<dim3(TT / 64, TT / 64, BB * HH), 256>>>(ptmp, pS);
        softmax_causal<<<BB * HH * TT, 128>>>(pS);
        attn_pv<<<dim3(1, TT / 64, BB * HH), 256>>>(pS, ptmp, py);
        sgemm_nt<true><<<dim3(DD / 128, BT / 128), 256>>>(
            py, w_proj + (size_t)l * DD * DD, px, BT, DD, DD);
        // mlp block
        layernorm_kernel<<<BT, 256>>>(px, ln2_g + l * DD, ln2_b + l * DD, pxn);
        sgemm_nt<false><<<dim3(FF / 128, BT / 128), 256>>>(
            pxn, w_fc + (size_t)l * FF * DD, ptmp, BT, FF, DD);
        gelu_kernel<<<(BT * FF) / (256 * 4), 256>>>(ptmp);
        sgemm_nt<true><<<dim3(DD / 128, BT / 128), 256>>>(
            ptmp, w_out + (size_t)l * DD * FF, px, BT, DD, FF);
    }

    // final LN + lm_head
    layernorm_kernel<<<BT, 256>>>(px, lnf_g, lnf_b, pxn);
    sgemm_nt<false><<<dim3((VV + 127) / 128, BT / 128), 256>>>(
        pxn, wte, out, BT, VV, DD);

    // cross-entropy loss
    loss_row_kernel<<<BT, 256>>>(out, targets, pnll);
    long long lidx = (long long)BT * VV;
    loss_reduce_kernel<<<1, 256>>>(pnll, targets, out, lidx,
                                   (long long)out_size - 1, (long long)out_size);
}

// round 10
// speedup vs baseline: 2.4001x; 2.4001x over previous
#include <cuda_runtime.h>
#include <cuda_bf16.h>
#include <math.h>
#include <stdint.h>

#define BB 4
#define TT 1024
#define DD 1024
#define HH 16
#define HD 64
#define LL 8
#define VV 50257
#define FF 4096
#define D3 3072
#define BT 4096   // B*T

// ---------------- scratch (static device globals; no allocation) ----------------
__device__ float g_x  [(size_t)BT * DD];   // residual stream
__device__ float g_xn [(size_t)BT * DD];   // layernorm output
__device__ float g_tmp[(size_t)BT * FF];   // qkv ([BT,3072]) or mlp hidden ([BT,4096])
__device__ float g_y  [(size_t)BT * DD];   // attention output (pre-proj)
__device__ float g_S  [(size_t)BB * HH * TT * TT]; // attention scores/probs
__device__ float g_nll[BT];

// ---------------- helpers ----------------
__device__ __forceinline__ uint32_t sptr(const void* p) {
    return (uint32_t)__cvta_generic_to_shared(p);
}
__device__ __forceinline__ void cpasync16(uint32_t dst, const float* src, int srcsize) {
    asm volatile("cp.async.cg.shared.global [%0], [%1], 16, %2;\n"
                 :: "r"(dst), "l"(src), "r"(srcsize));
}
__device__ __forceinline__ uint32_t f2tf32(float f) {
    uint32_t u;
    asm("cvt.rna.tf32.f32 %0, %1;" : "=r"(u) : "f"(f));
    return u;
}
__device__ __forceinline__ float gelu_exact(float x) {
    return 0.5f * x * (1.0f + erff(x * 0.70710678118654752f));
}

__device__ __forceinline__ float blockReduceSum(float v, float* red) {
    int tid = threadIdx.x;
    red[tid] = v; __syncthreads();
    for (int s = blockDim.x >> 1; s > 0; s >>= 1) {
        if (tid < s) red[tid] += red[tid + s];
        __syncthreads();
    }
    float r = red[0]; __syncthreads();
    return r;
}
__device__ __forceinline__ float blockReduceMax(float v, float* red) {
    int tid = threadIdx.x;
    red[tid] = v; __syncthreads();
    for (int s = blockDim.x >> 1; s > 0; s >>= 1) {
        if (tid < s) red[tid] = fmaxf(red[tid], red[tid + s]);
        __syncthreads();
    }
    float r = red[0]; __syncthreads();
    return r;
}

// ---------------- embedding ----------------
__global__ void embed_kernel(const int* __restrict__ ctx,
                             const float* __restrict__ wte,
                             const float* __restrict__ wpe,
                             float* __restrict__ x) {
    int r = blockIdx.x;
    int tok = ctx[r];
    int t = r & (TT - 1);
    const float* we = wte + (size_t)tok * DD;
    const float* wp = wpe + (size_t)t * DD;
    float* xr = x + (size_t)r * DD;
    for (int c = threadIdx.x; c < DD; c += blockDim.x)
        xr[c] = we[c] + wp[c];
}

// ---------------- layernorm ----------------
__global__ void layernorm_kernel(const float* __restrict__ x,
                                 const float* __restrict__ g,
                                 const float* __restrict__ b,
                                 float* __restrict__ o) {
    __shared__ float red[256];
    int r = blockIdx.x;
    const float* xr = x + (size_t)r * DD;
    float v[4];
    float s = 0.f, ss = 0.f;
#pragma unroll
    for (int k = 0; k < 4; k++) {
        int c = threadIdx.x + k * 256;
        v[k] = xr[c];
        s += v[k];
        ss += v[k] * v[k];
    }
    s  = blockReduceSum(s,  red);
    ss = blockReduceSum(ss, red);
    float mean = s * (1.0f / DD);
    float var  = ss * (1.0f / DD) - mean * mean;
    float rstd = rsqrtf(var + 1e-5f);
    float* orow = o + (size_t)r * DD;
#pragma unroll
    for (int k = 0; k < 4; k++) {
        int c = threadIdx.x + k * 256;
        orow[c] = (v[k] - mean) * rstd * g[c] + b[c];
    }
}

// ============ TF32 tensor-core GEMM: C[M,N] = A[M,K] @ W[N,K]^T =============
// Optional += (ADD) or exact-GELU epilogue (GELU). 128x128 CTA tile, BK=16,
// 2-stage cp.async pipeline, 8 warps of 64x32. mma.sync.m16n8k8 tf32.
// k-permutation (t->2t, t+4->2t+1) applied to BOTH A and B fragments so every
// fragment load is a float2 (legal: dot product is k-permutation invariant).
// M%128==0, K%16==0 required; N ragged allowed.
#define GSTRIDE 20   // 16 + 4 pad floats; 80B rows keep 16B cp.async alignment
#define GSTAGE_B (128 * GSTRIDE * 4)

template <bool ADD, bool GELU>
__global__ void __launch_bounds__(256, 2)
tf32gemm_nt(const float* __restrict__ A,
            const float* __restrict__ W,
            float* __restrict__ C,
            int M, int N, int K) {
    __shared__ __align__(16) float As[2][128][GSTRIDE];
    __shared__ __align__(16) float Ws[2][128][GSTRIDE];

    const int tid  = threadIdx.x;
    const int m0   = blockIdx.y * 128;
    const int n0   = blockIdx.x * 128;
    const int wid  = tid >> 5, lane = tid & 31;
    const int wm   = wid >> 2;          // 0..1
    const int wn   = wid & 3;           // 0..3
    const int g    = lane >> 2;         // 0..7
    const int t    = lane & 3;          // 0..3

    // global->smem copy coords: each thread copies 2 float4 of A and 2 of W
    const int lrow = tid >> 2;          // 0..63
    const int lcol = (tid & 3) * 4;     // 0,4,8,12
    const float* gA0 = A + (size_t)(m0 + lrow)      * K + lcol;
    const float* gA1 = A + (size_t)(m0 + lrow + 64) * K + lcol;
    const int nr0 = n0 + lrow, nr1 = n0 + lrow + 64;
    const float* gW0 = W + (size_t)(nr0 < N ? nr0 : 0) * K + lcol;
    const float* gW1 = W + (size_t)(nr1 < N ? nr1 : 0) * K + lcol;
    const int p0 = (nr0 < N) ? 16 : 0;
    const int p1 = (nr1 < N) ? 16 : 0;

    const uint32_t sA0 = sptr(&As[0][lrow][lcol]);
    const uint32_t sA1 = sptr(&As[0][lrow + 64][lcol]);
    const uint32_t sW0 = sptr(&Ws[0][lrow][lcol]);
    const uint32_t sW1 = sptr(&Ws[0][lrow + 64][lcol]);

    float acc[4][4][4];
#pragma unroll
    for (int a = 0; a < 4; a++)
#pragma unroll
        for (int b = 0; b < 4; b++)
#pragma unroll
            for (int c = 0; c < 4; c++) acc[a][b][c] = 0.f;

    const int NK = K >> 4;

    // prologue: stage 0
    cpasync16(sA0, gA0, 16);
    cpasync16(sA1, gA1, 16);
    cpasync16(sW0, gW0, p0);
    cpasync16(sW1, gW1, p1);
    asm volatile("cp.async.commit_group;\n" ::: "memory");

    for (int ks = 0; ks < NK; ks++) {
        if (ks + 1 < NK) {
            int so = ((ks + 1) & 1) * GSTAGE_B;
            int ko = (ks + 1) << 4;
            cpasync16(sA0 + so, gA0 + ko, 16);
            cpasync16(sA1 + so, gA1 + ko, 16);
            cpasync16(sW0 + so, gW0 + ko, p0);
            cpasync16(sW1 + so, gW1 + ko, p1);
            asm volatile("cp.async.commit_group;\n" ::: "memory");
            asm volatile("cp.async.wait_group 1;\n" ::: "memory");
        } else {
            asm volatile("cp.async.wait_group 0;\n" ::: "memory");
        }
        __syncthreads();

        const int buf = ks & 1;
#pragma unroll
        for (int kk = 0; kk < 16; kk += 8) {
            float2 av[4][2];
            float2 bv[4];
#pragma unroll
            for (int mt = 0; mt < 4; mt++) {
                av[mt][0] = *(const float2*)&As[buf][wm * 64 + mt * 16 + g][kk + 2 * t];
                av[mt][1] = *(const float2*)&As[buf][wm * 64 + mt * 16 + 8 + g][kk + 2 * t];
            }
#pragma unroll
            for (int nt = 0; nt < 4; nt++)
                bv[nt] = *(const float2*)&Ws[buf][wn * 32 + nt * 8 + g][kk + 2 * t];

            uint32_t au[4][4], bu[4][2];
#pragma unroll
            for (int mt = 0; mt < 4; mt++) {
                au[mt][0] = f2tf32(av[mt][0].x);
                au[mt][1] = f2tf32(av[mt][1].x);
                au[mt][2] = f2tf32(av[mt][0].y);
                au[mt][3] = f2tf32(av[mt][1].y);
            }
#pragma unroll
            for (int nt = 0; nt < 4; nt++) {
                bu[nt][0] = f2tf32(bv[nt].x);
                bu[nt][1] = f2tf32(bv[nt].y);
            }
#pragma unroll
            for (int mt = 0; mt < 4; mt++)
#pragma unroll
                for (int nt = 0; nt < 4; nt++) {
                    asm volatile(
                        "mma.sync.aligned.m16n8k8.row.col.f32.tf32.tf32.f32 "
                        "{%0,%1,%2,%3}, {%4,%5,%6,%7}, {%8,%9}, {%0,%1,%2,%3};\n"
                        : "+f"(acc[mt][nt][0]), "+f"(acc[mt][nt][1]),
                          "+f"(acc[mt][nt][2]), "+f"(acc[mt][nt][3])
                        : "r"(au[mt][0]), "r"(au[mt][1]), "r"(au[mt][2]), "r"(au[mt][3]),
                          "r"(bu[nt][0]), "r"(bu[nt][1]));
                }
        }
        __syncthreads();
    }

    // epilogue: c0,c1 -> (row g, cols 2t,2t+1); c2,c3 -> (row g+8, same cols)
#pragma unroll
    for (int mt = 0; mt < 4; mt++) {
        int m = m0 + wm * 64 + mt * 16 + g;
        float* r0 = C + (size_t)m * N;
        float* r1 = C + (size_t)(m + 8) * N;
#pragma unroll
        for (int nt = 0; nt < 4; nt++) {
            int n = n0 + wn * 32 + nt * 8 + 2 * t;
            float v0 = acc[mt][nt][0], v1 = acc[mt][nt][1];
            float v2 = acc[mt][nt][2], v3 = acc[mt][nt][3];
            if (GELU) {
                v0 = gelu_exact(v0); v1 = gelu_exact(v1);
                v2 = gelu_exact(v2); v3 = gelu_exact(v3);
            }
            if (ADD) {
                if (n     < N) r0[n]     += v0;
                if (n + 1 < N) r0[n + 1] += v1;
                if (n     < N) r1[n]     += v2;
                if (n + 1 < N) r1[n + 1] += v3;
            } else {
                if (n     < N) r0[n]     = v0;
                if (n + 1 < N) r0[n + 1] = v1;
                if (n     < N) r1[n]     = v2;
                if (n + 1 < N) r1[n + 1] = v3;
            }
        }
    }
}

// ---------------- attention scores: S = Q K^T / 8 (causal tiles only) -------
__global__ void attn_scores(const float* __restrict__ qkv, float* __restrict__ S) {
    int mt = blockIdx.y, nt = blockIdx.x;
    if (nt > mt) return;
    int bh = blockIdx.z;
    int b = bh >> 4, h = bh & 15;
    __shared__ float Qs[16][64];
    __shared__ float Ks[16][64];
    int tid = threadIdx.x;
    int lr = tid >> 2;
    int lk = (tid & 3) * 4;
    int ty = tid >> 4, tx = tid & 15;

    const float* qb = qkv + ((size_t)(b * TT + mt * 64 + lr)) * D3 + h * HD + lk;
    const float* kb = qkv + ((size_t)(b * TT + nt * 64 + lr)) * D3 + DD + h * HD + lk;

    float acc[4][4];
#pragma unroll
    for (int i = 0; i < 4; i++)
#pragma unroll
        for (int j = 0; j < 4; j++) acc[i][j] = 0.f;

    for (int k0 = 0; k0 < HD; k0 += 16) {
        float4 qv = *(const float4*)(qb + k0);
        float4 kv = *(const float4*)(kb + k0);
        __syncthreads();
        Qs[lk + 0][lr] = qv.x; Qs[lk + 1][lr] = qv.y;
        Qs[lk + 2][lr] = qv.z; Qs[lk + 3][lr] = qv.w;
        Ks[lk + 0][lr] = kv.x; Ks[lk + 1][lr] = kv.y;
        Ks[lk + 2][lr] = kv.z; Ks[lk + 3][lr] = kv.w;
        __syncthreads();
#pragma unroll
        for (int kk = 0; kk < 16; kk++) {
            float ra[4], rb[4];
#pragma unroll
            for (int i = 0; i < 4; i++) ra[i] = Qs[kk][ty * 4 + i];
#pragma unroll
            for (int j = 0; j < 4; j++) rb[j] = Ks[kk][tx * 4 + j];
#pragma unroll
            for (int i = 0; i < 4; i++)
#pragma unroll
                for (int j = 0; j < 4; j++) acc[i][j] = fmaf(ra[i], rb[j], acc[i][j]);
        }
    }
#pragma unroll
    for (int i = 0; i < 4; i++) {
        int t = mt * 64 + ty * 4 + i;
        float* srow = S + ((size_t)bh * TT + t) * TT;
#pragma unroll
        for (int j = 0; j < 4; j++) {
            int s = nt * 64 + tx * 4 + j;
            srow[s] = acc[i][j] * 0.125f;
        }
    }
}

// ---------------- causal softmax ----------------
__global__ void softmax_causal(float* __restrict__ S) {
    __shared__ float red[128];
    int row = blockIdx.x;
    int t = row & (TT - 1);
    float* p = S + (size_t)row * TT;
    int len = t + 1;
    int tid = threadIdx.x;

    float mx = -INFINITY;
    for (int i = tid; i < len; i += 128) mx = fmaxf(mx, p[i]);
    mx = blockReduceMax(mx, red);

    float s = 0.f;
    for (int i = tid; i < len; i += 128) {
        float e = expf(p[i] - mx);
        p[i] = e;
        s += e;
    }
    s = blockReduceSum(s, red);
    float inv = 1.0f / s;
    for (int i = tid; i < len; i += 128) p[i] *= inv;
    int fill = ((t >> 6) + 1) << 6;
    for (int i = len + tid; i < fill; i += 128) p[i] = 0.f;
}

// ---------------- attention PV ----------------
__global__ void attn_pv(const float* __restrict__ S,
                        const float* __restrict__ qkv,
                        float* __restrict__ y) {
    int mt = blockIdx.y;
    int bh = blockIdx.z;
    int b = bh >> 4, h = bh & 15;
    __shared__ float Ps[16][64];
    __shared__ float Vs[16][64];
    int tid = threadIdx.x;
    int ty = tid >> 4, tx = tid & 15;

    int lr = tid >> 2;
    int ls = (tid & 3) * 4;
    int vk = tid >> 4;
    int vd = (tid & 15) * 4;

    const float* Pb = S + ((size_t)bh * TT + mt * 64 + lr) * TT + ls;
    const float* Vb = qkv + ((size_t)(b * TT + vk)) * D3 + 2 * DD + h * HD + vd;

    float acc[4][4];
#pragma unroll
    for (int i = 0; i < 4; i++)
#pragma unroll
        for (int j = 0; j < 4; j++) acc[i][j] = 0.f;

    int send = (mt + 1) * 64;
    for (int s0 = 0; s0 < send; s0 += 16) {
        float4 pv = *(const float4*)(Pb + s0);
        float4 vv = *(const float4*)(Vb + (size_t)s0 * D3);
        __syncthreads();
        Ps[ls + 0][lr] = pv.x; Ps[ls + 1][lr] = pv.y;
        Ps[ls + 2][lr] = pv.z; Ps[ls + 3][lr] = pv.w;
        Vs[vk][vd + 0] = vv.x; Vs[vk][vd + 1] = vv.y;
        Vs[vk][vd + 2] = vv.z; Vs[vk][vd + 3] = vv.w;
        __syncthreads();
#pragma unroll
        for (int kk = 0; kk < 16; kk++) {
            float ra[4], rb[4];
#pragma unroll
            for (int i = 0; i < 4; i++) ra[i] = Ps[kk][ty * 4 + i];
#pragma unroll
            for (int j = 0; j < 4; j++) rb[j] = Vs[kk][tx * 4 + j];
#pragma unroll
            for (int i = 0; i < 4; i++)
#pragma unroll
                for (int j = 0; j < 4; j++) acc[i][j] = fmaf(ra[i], rb[j], acc[i][j]);
        }
    }
#pragma unroll
    for (int i = 0; i < 4; i++) {
        int t = mt * 64 + ty * 4 + i;
        float* yr = y + ((size_t)(b * TT + t)) * DD + h * HD;
#pragma unroll
        for (int j = 0; j < 4; j++) yr[tx * 4 + j] = acc[i][j];
    }
}

// ---------------- cross entropy ----------------
__global__ void loss_row_kernel(const float* __restrict__ logits,
                                const int* __restrict__ targets,
                                float* __restrict__ nll) {
    __shared__ float red[256];
    int r = blockIdx.x;
    const float* p = logits + (size_t)r * VV;
    int tid = threadIdx.x;
    float mx = -INFINITY;
    for (int i = tid; i < VV; i += 256) mx = fmaxf(mx, p[i]);
    mx = blockReduceMax(mx, red);
    float s = 0.f;
    for (int i = tid; i < VV; i += 256) s += expf(p[i] - mx);
    s = blockReduceSum(s, red);
    if (tid == 0) {
        int tg = targets[r];
        nll[r] = (tg < 0) ? 0.f : (logf(s) + mx - p[tg]);
    }
}

__global__ void loss_reduce_kernel(const float* __restrict__ nll,
                                   const int* __restrict__ targets,
                                   float* __restrict__ out,
                                   long long idx1, long long idx2, long long out_size) {
    __shared__ float red[256];
    __shared__ float redc[256];
    int tid = threadIdx.x;
    float acc = 0.f, cnt = 0.f;
    for (int i = tid; i < BT; i += 256) {
        acc += nll[i];
        cnt += (targets[i] != -1) ? 1.f : 0.f;
    }
    red[tid] = acc; redc[tid] = cnt; __syncthreads();
    for (int s = 128; s > 0; s >>= 1) {
        if (tid < s) { red[tid] += red[tid + s]; redc[tid] += redc[tid + s]; }
        __syncthreads();
    }
    if (tid == 0) {
        float loss = red[0] / fmaxf(redc[0], 1.f);
        if (idx1 >= 0 && idx1 < out_size) out[idx1] = loss;
        if (idx2 != idx1 && idx2 >= (long long)BT * VV && idx2 < out_size) out[idx2] = loss;
    }
}

// ---------------- driver ----------------
extern "C" void kernel_launch(void* const* d_in, const int* in_sizes, int n_in,
                              void* d_out, int out_size) {
    const int*   context = (const int*)  d_in[0];
    const int*   targets = (const int*)  d_in[1];
    const float* wte     = (const float*)d_in[2];
    const float* wpe     = (const float*)d_in[3];
    const float* ln1_g   = (const float*)d_in[4];
    const float* ln1_b   = (const float*)d_in[5];
    const float* w_attn  = (const float*)d_in[6];
    const float* w_proj  = (const float*)d_in[7];
    const float* ln2_g   = (const float*)d_in[8];
    const float* ln2_b   = (const float*)d_in[9];
    const float* w_fc    = (const float*)d_in[10];
    const float* w_out   = (const float*)d_in[11];
    const float* lnf_g   = (const float*)d_in[12];
    const float* lnf_b   = (const float*)d_in[13];
    float* out = (float*)d_out;

    float *px, *pxn, *ptmp, *py, *pS, *pnll;
    cudaGetSymbolAddress((void**)&px,   g_x);
    cudaGetSymbolAddress((void**)&pxn,  g_xn);
    cudaGetSymbolAddress((void**)&ptmp, g_tmp);
    cudaGetSymbolAddress((void**)&py,   g_y);
    cudaGetSymbolAddress((void**)&pS,   g_S);
    cudaGetSymbolAddress((void**)&pnll, g_nll);

    embed_kernel<<<BT, 256>>>(context, wte, wpe, px);

    for (int l = 0; l < LL; l++) {
        // attention block
        layernorm_kernel<<<BT, 256>>>(px, ln1_g + l * DD, ln1_b + l * DD, pxn);
        tf32gemm_nt<false, false><<<dim3(D3 / 128, BT / 128), 256>>>(
            pxn, w_attn + (size_t)l * D3 * DD, ptmp, BT, D3, DD);
        attn_scores<<<dim3(TT / 64, TT / 64, BB * HH), 256>>>(ptmp, pS);
        softmax_causal<<<BB * HH * TT, 128>>>(pS);
        attn_pv<<<dim3(1, TT / 64, BB * HH), 256>>>(pS, ptmp, py);
        tf32gemm_nt<true, false><<<dim3(DD / 128, BT / 128), 256>>>(
            py, w_proj + (size_t)l * DD * DD, px, BT, DD, DD);
        // mlp block (GELU fused into fc epilogue)
        layernorm_kernel<<<BT, 256>>>(px, ln2_g + l * DD, ln2_b + l * DD, pxn);
        tf32gemm_nt<false, true><<<dim3(FF / 128, BT / 128), 256>>>(
            pxn, w_fc + (size_t)l * FF * DD, ptmp, BT, FF, DD);
        tf32gemm_nt<true, false><<<dim3(DD / 128, BT / 128), 256>>>(
            ptmp, w_out + (size_t)l * DD * FF, px, BT, DD, FF);
    }

    // final LN + lm_head
    layernorm_kernel<<<BT, 256>>>(px, lnf_g, lnf_b, pxn);
    tf32gemm_nt<false, false><<<dim3((VV + 127) / 128, BT / 128), 256>>>(
        pxn, wte, out, BT, VV, DD);

    // cross-entropy loss
    loss_row_kernel<<<BT, 256>>>(out, targets, pnll);
    long long lidx = (long long)BT * VV;
    loss_reduce_kernel<<<1, 256>>>(pnll, targets, out, lidx,
                                   (long long)out_size - 1, (long long)out_size);
}

// round 11
// speedup vs baseline: 2.4637x; 1.0265x over previous
#include <cuda_runtime.h>
#include <cuda_bf16.h>
#include <math.h>
#include <stdint.h>

#define BB 4
#define TT 1024
#define DD 1024
#define HH 16
#define HD 64
#define LL 8
#define VV 50257
#define FF 4096
#define D3 3072
#define BT 4096   // B*T

// ---------------- scratch (static device globals; no allocation) ----------------
__device__ float g_x  [(size_t)BT * DD];
__device__ float g_xn [(size_t)BT * DD];
__device__ float g_tmp[(size_t)BT * FF];
__device__ float g_y  [(size_t)BT * DD];
__device__ float g_S  [(size_t)BB * HH * TT * TT];
__device__ float g_nll[BT];
__device__ float g_cvtW[(size_t)VV * DD];   // tf32-rounded weight staging (max = wte)

// ---------------- helpers ----------------
__device__ __forceinline__ uint32_t sptr(const void* p) {
    return (uint32_t)__cvta_generic_to_shared(p);
}
__device__ __forceinline__ void cpasync16(uint32_t dst, const float* src, int srcsize) {
    asm volatile("cp.async.cg.shared.global [%0], [%1], 16, %2;\n"
                 :: "r"(dst), "l"(src), "r"(srcsize));
}
__device__ __forceinline__ uint32_t f2tf32(float f) {
    uint32_t u;
    asm("cvt.rna.tf32.f32 %0, %1;" : "=r"(u) : "f"(f));
    return u;
}
__device__ __forceinline__ float round_tf32(float f) {
    return __uint_as_float(f2tf32(f));
}
__device__ __forceinline__ float gelu_exact(float x) {
    return 0.5f * x * (1.0f + erff(x * 0.70710678118654752f));
}

__device__ __forceinline__ float blockReduceSum(float v, float* red) {
    int tid = threadIdx.x;
    red[tid] = v; __syncthreads();
    for (int s = blockDim.x >> 1; s > 0; s >>= 1) {
        if (tid < s) red[tid] += red[tid + s];
        __syncthreads();
    }
    float r = red[0]; __syncthreads();
    return r;
}
__device__ __forceinline__ float blockReduceMax(float v, float* red) {
    int tid = threadIdx.x;
    red[tid] = v; __syncthreads();
    for (int s = blockDim.x >> 1; s > 0; s >>= 1) {
        if (tid < s) red[tid] = fmaxf(red[tid], red[tid + s]);
        __syncthreads();
    }
    float r = red[0]; __syncthreads();
    return r;
}

// ---------------- weight tf32 pre-round ----------------
__global__ void cvt_tf32_kernel(const float4* __restrict__ in,
                                float4* __restrict__ out, int n4) {
    int stride = gridDim.x * blockDim.x;
    for (int i = blockIdx.x * blockDim.x + threadIdx.x; i < n4; i += stride) {
        float4 v = in[i];
        v.x = round_tf32(v.x);
        v.y = round_tf32(v.y);
        v.z = round_tf32(v.z);
        v.w = round_tf32(v.w);
        out[i] = v;
    }
}

// ---------------- embedding ----------------
__global__ void embed_kernel(const int* __restrict__ ctx,
                             const float* __restrict__ wte,
                             const float* __restrict__ wpe,
                             float* __restrict__ x) {
    int r = blockIdx.x;
    int tok = ctx[r];
    int t = r & (TT - 1);
    const float* we = wte + (size_t)tok * DD;
    const float* wp = wpe + (size_t)t * DD;
    float* xr = x + (size_t)r * DD;
    for (int c = threadIdx.x; c < DD; c += blockDim.x)
        xr[c] = we[c] + wp[c];
}

// ---------------- layernorm (output tf32-rounded: feeds GEMM-A only) -------
__global__ void layernorm_kernel(const float* __restrict__ x,
                                 const float* __restrict__ g,
                                 const float* __restrict__ b,
                                 float* __restrict__ o) {
    __shared__ float red[256];
    int r = blockIdx.x;
    const float* xr = x + (size_t)r * DD;
    float v[4];
    float s = 0.f, ss = 0.f;
#pragma unroll
    for (int k = 0; k < 4; k++) {
        int c = threadIdx.x + k * 256;
        v[k] = xr[c];
        s += v[k];
        ss += v[k] * v[k];
    }
    s  = blockReduceSum(s,  red);
    ss = blockReduceSum(ss, red);
    float mean = s * (1.0f / DD);
    float var  = ss * (1.0f / DD) - mean * mean;
    float rstd = rsqrtf(var + 1e-5f);
    float* orow = o + (size_t)r * DD;
#pragma unroll
    for (int k = 0; k < 4; k++) {
        int c = threadIdx.x + k * 256;
        orow[c] = round_tf32((v[k] - mean) * rstd * g[c] + b[c]);
    }
}

// ============ TF32 tensor-core GEMM: C[M,N] = A[M,K] @ W[N,K]^T =============
// Inputs pre-rounded to tf32 (no in-loop cvt). 128x128 CTA tile, BK=16,
// 4-stage cp.async pipeline (dynamic smem 80KB), single barrier per k-step,
// 8 warps of 64x32. k-permutation: thread t owns physical cols {4t..4t+3} of
// each 16-chunk; float4 .xy feed MMA0, .zw feed MMA1 (same permutation on A
// and B -> exact). M%128==0, K%16==0; N ragged allowed.
#define GSTRIDE 20                       // 16 + 4 pad floats (80B rows)
#define STAGEF  (128 * GSTRIDE)          // floats per matrix per stage
#define STAGE_BYTES (2 * STAGEF * 4)     // A + W = 20480 B
#define GEMM_SMEM_BYTES (4 * STAGE_BYTES) // 81920 B

template <bool ADD, bool GELU>
__global__ void __launch_bounds__(256, 2)
tf32gemm_nt(const float* __restrict__ A,
            const float* __restrict__ W,
            float* __restrict__ C,
            int M, int N, int K) {
    extern __shared__ __align__(16) float sm[];

    const int tid  = threadIdx.x;
    const int m0   = blockIdx.y * 128;
    const int n0   = blockIdx.x * 128;
    const int wid  = tid >> 5, lane = tid & 31;
    const int wm   = wid >> 2;          // 0..1
    const int wn   = wid & 3;           // 0..3
    const int g    = lane >> 2;         // 0..7
    const int t    = lane & 3;          // 0..3

    const int lrow = tid >> 2;          // 0..63
    const int lcol = (tid & 3) * 4;     // 0,4,8,12
    const float* gA0 = A + (size_t)(m0 + lrow)      * K + lcol;
    const float* gA1 = A + (size_t)(m0 + lrow + 64) * K + lcol;
    const int nr0 = n0 + lrow, nr1 = n0 + lrow + 64;
    const float* gW0 = W + (size_t)(nr0 < N ? nr0 : 0) * K + lcol;
    const float* gW1 = W + (size_t)(nr1 < N ? nr1 : 0) * K + lcol;
    const int p0 = (nr0 < N) ? 16 : 0;
    const int p1 = (nr1 < N) ? 16 : 0;

    const uint32_t sbase = sptr(sm);
    const uint32_t offA0 = (uint32_t)(lrow * GSTRIDE + lcol) * 4;
    const uint32_t offA1 = (uint32_t)((lrow + 64) * GSTRIDE + lcol) * 4;
    const uint32_t offW0 = (uint32_t)(STAGEF + lrow * GSTRIDE + lcol) * 4;
    const uint32_t offW1 = (uint32_t)(STAGEF + (lrow + 64) * GSTRIDE + lcol) * 4;

    float acc[4][4][4];
#pragma unroll
    for (int a = 0; a < 4; a++)
#pragma unroll
        for (int b = 0; b < 4; b++)
#pragma unroll
            for (int c = 0; c < 4; c++) acc[a][b][c] = 0.f;

    const int NK = K >> 4;

#define G_ISSUE(stage, k0) do {                         \
    uint32_t sb = sbase + (uint32_t)(stage) * STAGE_BYTES; \
    cpasync16(sb + offA0, gA0 + (k0), 16);              \
    cpasync16(sb + offA1, gA1 + (k0), 16);              \
    cpasync16(sb + offW0, gW0 + (k0), p0);              \
    cpasync16(sb + offW1, gW1 + (k0), p1);              \
} while (0)

    // prologue: 3 stages in flight
    G_ISSUE(0, 0);
    asm volatile("cp.async.commit_group;\n" ::: "memory");
    G_ISSUE(1, 16);
    asm volatile("cp.async.commit_group;\n" ::: "memory");
    G_ISSUE(2, 32);
    asm volatile("cp.async.commit_group;\n" ::: "memory");

    for (int ks = 0; ks < NK; ks++) {
        asm volatile("cp.async.wait_group 2;\n" ::: "memory");
        __syncthreads();   // stage ks visible block-wide; stage ks-1 free
        int pf = ks + 3;
        if (pf < NK) G_ISSUE(pf & 3, pf << 4);
        asm volatile("cp.async.commit_group;\n" ::: "memory");

        const float* As = sm + (size_t)(ks & 3) * 2 * STAGEF;
        const float* Ws = As + STAGEF;

        float4 b[4];
#pragma unroll
        for (int nt = 0; nt < 4; nt++)
            b[nt] = *(const float4*)&Ws[(wn * 32 + nt * 8 + g) * GSTRIDE + 4 * t];

#pragma unroll
        for (int mt = 0; mt < 4; mt++) {
            float4 a0 = *(const float4*)&As[(wm * 64 + mt * 16 + g) * GSTRIDE + 4 * t];
            float4 a1 = *(const float4*)&As[(wm * 64 + mt * 16 + 8 + g) * GSTRIDE + 4 * t];
#pragma unroll
            for (int nt = 0; nt < 4; nt++) {
                asm volatile(
                    "mma.sync.aligned.m16n8k8.row.col.f32.tf32.tf32.f32 "
                    "{%0,%1,%2,%3}, {%4,%5,%6,%7}, {%8,%9}, {%0,%1,%2,%3};\n"
                    : "+f"(acc[mt][nt][0]), "+f"(acc[mt][nt][1]),
                      "+f"(acc[mt][nt][2]), "+f"(acc[mt][nt][3])
                    : "r"(__float_as_uint(a0.x)), "r"(__float_as_uint(a1.x)),
                      "r"(__float_as_uint(a0.y)), "r"(__float_as_uint(a1.y)),
                      "r"(__float_as_uint(b[nt].x)), "r"(__float_as_uint(b[nt].y)));
                asm volatile(
                    "mma.sync.aligned.m16n8k8.row.col.f32.tf32.tf32.f32 "
                    "{%0,%1,%2,%3}, {%4,%5,%6,%7}, {%8,%9}, {%0,%1,%2,%3};\n"
                    : "+f"(acc[mt][nt][0]), "+f"(acc[mt][nt][1]),
                      "+f"(acc[mt][nt][2]), "+f"(acc[mt][nt][3])
                    : "r"(__float_as_uint(a0.z)), "r"(__float_as_uint(a1.z)),
                      "r"(__float_as_uint(a0.w)), "r"(__float_as_uint(a1.w)),
                      "r"(__float_as_uint(b[nt].z)), "r"(__float_as_uint(b[nt].w)));
            }
        }
    }
#undef G_ISSUE

    // epilogue: c0,c1 -> (row g, cols 2t,2t+1); c2,c3 -> (row g+8, same cols)
#pragma unroll
    for (int mt = 0; mt < 4; mt++) {
        int m = m0 + wm * 64 + mt * 16 + g;
        float* r0 = C + (size_t)m * N;
        float* r1 = C + (size_t)(m + 8) * N;
#pragma unroll
        for (int nt = 0; nt < 4; nt++) {
            int n = n0 + wn * 32 + nt * 8 + 2 * t;
            float v0 = acc[mt][nt][0], v1 = acc[mt][nt][1];
            float v2 = acc[mt][nt][2], v3 = acc[mt][nt][3];
            if (GELU) {  // feeds next GEMM's A: pre-round to tf32
                v0 = round_tf32(gelu_exact(v0)); v1 = round_tf32(gelu_exact(v1));
                v2 = round_tf32(gelu_exact(v2)); v3 = round_tf32(gelu_exact(v3));
            }
            if (ADD) {
                if (n     < N) r0[n]     += v0;
                if (n + 1 < N) r0[n + 1] += v1;
                if (n     < N) r1[n]     += v2;
                if (n + 1 < N) r1[n + 1] += v3;
            } else {
                if (n     < N) r0[n]     = v0;
                if (n + 1 < N) r0[n + 1] = v1;
                if (n     < N) r1[n]     = v2;
                if (n + 1 < N) r1[n + 1] = v3;
            }
        }
    }
}

// ---------------- attention scores: S = Q K^T / 8 (causal tiles only) -------
__global__ void attn_scores(const float* __restrict__ qkv, float* __restrict__ S) {
    int mt = blockIdx.y, nt = blockIdx.x;
    if (nt > mt) return;
    int bh = blockIdx.z;
    int b = bh >> 4, h = bh & 15;
    __shared__ float Qs[16][64];
    __shared__ float Ks[16][64];
    int tid = threadIdx.x;
    int lr = tid >> 2;
    int lk = (tid & 3) * 4;
    int ty = tid >> 4, tx = tid & 15;

    const float* qb = qkv + ((size_t)(b * TT + mt * 64 + lr)) * D3 + h * HD + lk;
    const float* kb = qkv + ((size_t)(b * TT + nt * 64 + lr)) * D3 + DD + h * HD + lk;

    float acc[4][4];
#pragma unroll
    for (int i = 0; i < 4; i++)
#pragma unroll
        for (int j = 0; j < 4; j++) acc[i][j] = 0.f;

    for (int k0 = 0; k0 < HD; k0 += 16) {
        float4 qv = *(const float4*)(qb + k0);
        float4 kv = *(const float4*)(kb + k0);
        __syncthreads();
        Qs[lk + 0][lr] = qv.x; Qs[lk + 1][lr] = qv.y;
        Qs[lk + 2][lr] = qv.z; Qs[lk + 3][lr] = qv.w;
        Ks[lk + 0][lr] = kv.x; Ks[lk + 1][lr] = kv.y;
        Ks[lk + 2][lr] = kv.z; Ks[lk + 3][lr] = kv.w;
        __syncthreads();
#pragma unroll
        for (int kk = 0; kk < 16; kk++) {
            float ra[4], rb[4];
#pragma unroll
            for (int i = 0; i < 4; i++) ra[i] = Qs[kk][ty * 4 + i];
#pragma unroll
            for (int j = 0; j < 4; j++) rb[j] = Ks[kk][tx * 4 + j];
#pragma unroll
            for (int i = 0; i < 4; i++)
#pragma unroll
                for (int j = 0; j < 4; j++) acc[i][j] = fmaf(ra[i], rb[j], acc[i][j]);
        }
    }
#pragma unroll
    for (int i = 0; i < 4; i++) {
        int t = mt * 64 + ty * 4 + i;
        float* srow = S + ((size_t)bh * TT + t) * TT;
#pragma unroll
        for (int j = 0; j < 4; j++) {
            int s = nt * 64 + tx * 4 + j;
            srow[s] = acc[i][j] * 0.125f;
        }
    }
}

// ---------------- causal softmax ----------------
__global__ void softmax_causal(float* __restrict__ S) {
    __shared__ float red[128];
    int row = blockIdx.x;
    int t = row & (TT - 1);
    float* p = S + (size_t)row * TT;
    int len = t + 1;
    int tid = threadIdx.x;

    float mx = -INFINITY;
    for (int i = tid; i < len; i += 128) mx = fmaxf(mx, p[i]);
    mx = blockReduceMax(mx, red);

    float s = 0.f;
    for (int i = tid; i < len; i += 128) {
        float e = expf(p[i] - mx);
        p[i] = e;
        s += e;
    }
    s = blockReduceSum(s, red);
    float inv = 1.0f / s;
    for (int i = tid; i < len; i += 128) p[i] *= inv;
    int fill = ((t >> 6) + 1) << 6;
    for (int i = len + tid; i < fill; i += 128) p[i] = 0.f;
}

// ---------------- attention PV (output tf32-rounded: feeds proj GEMM) ------
__global__ void attn_pv(const float* __restrict__ S,
                        const float* __restrict__ qkv,
                        float* __restrict__ y) {
    int mt = blockIdx.y;
    int bh = blockIdx.z;
    int b = bh >> 4, h = bh & 15;
    __shared__ float Ps[16][64];
    __shared__ float Vs[16][64];
    int tid = threadIdx.x;
    int ty = tid >> 4, tx = tid & 15;

    int lr = tid >> 2;
    int ls = (tid & 3) * 4;
    int vk = tid >> 4;
    int vd = (tid & 15) * 4;

    const float* Pb = S + ((size_t)bh * TT + mt * 64 + lr) * TT + ls;
    const float* Vb = qkv + ((size_t)(b * TT + vk)) * D3 + 2 * DD + h * HD + vd;

    float acc[4][4];
#pragma unroll
    for (int i = 0; i < 4; i++)
#pragma unroll
        for (int j = 0; j < 4; j++) acc[i][j] = 0.f;

    int send = (mt + 1) * 64;
    for (int s0 = 0; s0 < send; s0 += 16) {
        float4 pv = *(const float4*)(Pb + s0);
        float4 vv = *(const float4*)(Vb + (size_t)s0 * D3);
        __syncthreads();
        Ps[ls + 0][lr] = pv.x; Ps[ls + 1][lr] = pv.y;
        Ps[ls + 2][lr] = pv.z; Ps[ls + 3][lr] = pv.w;
        Vs[vk][vd + 0] = vv.x; Vs[vk][vd + 1] = vv.y;
        Vs[vk][vd + 2] = vv.z; Vs[vk][vd + 3] = vv.w;
        __syncthreads();
#pragma unroll
        for (int kk = 0; kk < 16; kk++) {
            float ra[4], rb[4];
#pragma unroll
            for (int i = 0; i < 4; i++) ra[i] = Ps[kk][ty * 4 + i];
#pragma unroll
            for (int j = 0; j < 4; j++) rb[j] = Vs[kk][tx * 4 + j];
#pragma unroll
            for (int i = 0; i < 4; i++)
#pragma unroll
                for (int j = 0; j < 4; j++) acc[i][j] = fmaf(ra[i], rb[j], acc[i][j]);
        }
    }
#pragma unroll
    for (int i = 0; i < 4; i++) {
        int t = mt * 64 + ty * 4 + i;
        float* yr = y + ((size_t)(b * TT + t)) * DD + h * HD;
#pragma unroll
        for (int j = 0; j < 4; j++) yr[tx * 4 + j] = round_tf32(acc[i][j]);
    }
}

// ---------------- cross entropy ----------------
__global__ void loss_row_kernel(const float* __restrict__ logits,
                                const int* __restrict__ targets,
                                float* __restrict__ nll) {
    __shared__ float red[256];
    int r = blockIdx.x;
    const float* p = logits + (size_t)r * VV;
    int tid = threadIdx.x;
    float mx = -INFINITY;
    for (int i = tid; i < VV; i += 256) mx = fmaxf(mx, p[i]);
    mx = blockReduceMax(mx, red);
    float s = 0.f;
    for (int i = tid; i < VV; i += 256) s += expf(p[i] - mx);
    s = blockReduceSum(s, red);
    if (tid == 0) {
        int tg = targets[r];
        nll[r] = (tg < 0) ? 0.f : (logf(s) + mx - p[tg]);
    }
}

__global__ void loss_reduce_kernel(const float* __restrict__ nll,
                                   const int* __restrict__ targets,
                                   float* __restrict__ out,
                                   long long idx1, long long idx2, long long out_size) {
    __shared__ float red[256];
    __shared__ float redc[256];
    int tid = threadIdx.x;
    float acc = 0.f, cnt = 0.f;
    for (int i = tid; i < BT; i += 256) {
        acc += nll[i];
        cnt += (targets[i] != -1) ? 1.f : 0.f;
    }
    red[tid] = acc; redc[tid] = cnt; __syncthreads();
    for (int s = 128; s > 0; s >>= 1) {
        if (tid < s) { red[tid] += red[tid + s]; redc[tid] += redc[tid + s]; }
        __syncthreads();
    }
    if (tid == 0) {
        float loss = red[0] / fmaxf(redc[0], 1.f);
        if (idx1 >= 0 && idx1 < out_size) out[idx1] = loss;
        if (idx2 != idx1 && idx2 >= (long long)BT * VV && idx2 < out_size) out[idx2] = loss;
    }
}

// ---------------- driver ----------------
extern "C" void kernel_launch(void* const* d_in, const int* in_sizes, int n_in,
                              void* d_out, int out_size) {
    const int*   context = (const int*)  d_in[0];
    const int*   targets = (const int*)  d_in[1];
    const float* wte     = (const float*)d_in[2];
    const float* wpe     = (const float*)d_in[3];
    const float* ln1_g   = (const float*)d_in[4];
    const float* ln1_b   = (const float*)d_in[5];
    const float* w_attn  = (const float*)d_in[6];
    const float* w_proj  = (const float*)d_in[7];
    const float* ln2_g   = (const float*)d_in[8];
    const float* ln2_b   = (const float*)d_in[9];
    const float* w_fc    = (const float*)d_in[10];
    const float* w_out   = (const float*)d_in[11];
    const float* lnf_g   = (const float*)d_in[12];
    const float* lnf_b   = (const float*)d_in[13];
    float* out = (float*)d_out;

    float *px, *pxn, *ptmp, *py, *pS, *pnll, *pcw;
    cudaGetSymbolAddress((void**)&px,   g_x);
    cudaGetSymbolAddress((void**)&pxn,  g_xn);
    cudaGetSymbolAddress((void**)&ptmp, g_tmp);
    cudaGetSymbolAddress((void**)&py,   g_y);
    cudaGetSymbolAddress((void**)&pS,   g_S);
    cudaGetSymbolAddress((void**)&pnll, g_nll);
    cudaGetSymbolAddress((void**)&pcw,  g_cvtW);

    cudaFuncSetAttribute(tf32gemm_nt<false, false>,
                         cudaFuncAttributeMaxDynamicSharedMemorySize, GEMM_SMEM_BYTES);
    cudaFuncSetAttribute(tf32gemm_nt<true, false>,
                         cudaFuncAttributeMaxDynamicSharedMemorySize, GEMM_SMEM_BYTES);
    cudaFuncSetAttribute(tf32gemm_nt<false, true>,
                         cudaFuncAttributeMaxDynamicSharedMemorySize, GEMM_SMEM_BYTES);

    embed_kernel<<<BT, 256>>>(context, wte, wpe, px);

    for (int l = 0; l < LL; l++) {
        // attention block
        layernorm_kernel<<<BT, 256>>>(px, ln1_g + l * DD, ln1_b + l * DD, pxn);
        cvt_tf32_kernel<<<1024, 256>>>(
            (const float4*)(w_attn + (size_t)l * D3 * DD), (float4*)pcw, D3 * DD / 4);
        tf32gemm_nt<false, false><<<dim3(D3 / 128, BT / 128), 256, GEMM_SMEM_BYTES>>>(
            pxn, pcw, ptmp, BT, D3, DD);
        attn_scores<<<dim3(TT / 64, TT / 64, BB * HH), 256>>>(ptmp, pS);
        softmax_causal<<<BB * HH * TT, 128>>>(pS);
        attn_pv<<<dim3(1, TT / 64, BB * HH), 256>>>(pS, ptmp, py);
        cvt_tf32_kernel<<<1024, 256>>>(
            (const float4*)(w_proj + (size_t)l * DD * DD), (float4*)pcw, DD * DD / 4);
        tf32gemm_nt<true, false><<<dim3(DD / 128, BT / 128), 256, GEMM_SMEM_BYTES>>>(
            py, pcw, px, BT, DD, DD);
        // mlp block (GELU fused into fc epilogue, tf32-rounded for next GEMM)
        layernorm_kernel<<<BT, 256>>>(px, ln2_g + l * DD, ln2_b + l * DD, pxn);
        cvt_tf32_kernel<<<1024, 256>>>(
            (const float4*)(w_fc + (size_t)l * FF * DD), (float4*)pcw, FF * DD / 4);
        tf32gemm_nt<false, true><<<dim3(FF / 128, BT / 128), 256, GEMM_SMEM_BYTES>>>(
            pxn, pcw, ptmp, BT, FF, DD);
        cvt_tf32_kernel<<<1024, 256>>>(
            (const float4*)(w_out + (size_t)l * DD * FF), (float4*)pcw, DD * FF / 4);
        tf32gemm_nt<true, false><<<dim3(DD / 128, BT / 128), 256, GEMM_SMEM_BYTES>>>(
            ptmp, pcw, px, BT, DD, FF);
    }

    // final LN + lm_head
    layernorm_kernel<<<BT, 256>>>(px, lnf_g, lnf_b, pxn);
    cvt_tf32_kernel<<<2048, 256>>>(
        (const float4*)wte, (float4*)pcw, VV * DD / 4);
    tf32gemm_nt<false, false><<<dim3((VV + 127) / 128, BT / 128), 256, GEMM_SMEM_BYTES>>>(
        pxn, pcw, out, BT, VV, DD);

    // cross-entropy loss
    loss_row_kernel<<<BT, 256>>>(out, targets, pnll);
    long long lidx = (long long)BT * VV;
    loss_reduce_kernel<<<1, 256>>>(pnll, targets, out, lidx,
                                   (long long)out_size - 1, (long long)out_size);
}